// round 2
// baseline (speedup 1.0000x reference)
#include <cuda_runtime.h>
#include <cstdint>

// ---------------- problem constants (fixed by the dataset) ----------------
#define MAX_N 50000
#define MAX_E 800000
#define D 128

// ---------------- device-global scratch (no allocations allowed) ----------
__device__ int   g_counts[MAX_N];
__device__ int   g_cursor[MAX_N];
__device__ int   g_rowptr[MAX_N + 1];
__device__ int   g_csr_src[MAX_E];
__device__ float g_invdeg[MAX_N];
__device__ float g_agg[(size_t)MAX_N * D];
__device__ float g_h[(size_t)MAX_N * D];

// ---------------- CSR build ----------------
__global__ void k_zero(int n) {
    int i = blockIdx.x * blockDim.x + threadIdx.x;
    if (i < n) { g_counts[i] = 0; g_cursor[i] = 0; }
}

// edge_index is int32 (JAX default config downgrades int64 -> int32).
__global__ void k_count(const int* __restrict__ ei, int E, int n) {
    int e = blockIdx.x * blockDim.x + threadIdx.x;
    if (e < E) {
        int d = ei[E + e];                  // dst row
        d = min(max(d, 0), n - 1);          // trap-proofing
        atomicAdd(&g_counts[d], 1);
    }
}

// single-block exclusive scan over counts -> rowptr; also inv_deg
__global__ __launch_bounds__(1024) void k_scan(int n) {
    __shared__ int wsum[32];
    __shared__ int carry_s;
    int tid  = threadIdx.x;
    int lane = tid & 31;
    int wid  = tid >> 5;
    if (tid == 0) carry_s = 0;
    __syncthreads();

    for (int base = 0; base < n; base += 1024) {
        int i = base + tid;
        int v = (i < n) ? g_counts[i] : 0;
        // warp inclusive scan
        int x = v;
        #pragma unroll
        for (int o = 1; o < 32; o <<= 1) {
            int t = __shfl_up_sync(0xFFFFFFFFu, x, o);
            if (lane >= o) x += t;
        }
        if (lane == 31) wsum[wid] = x;
        __syncthreads();
        if (wid == 0) {
            int y = wsum[lane];
            int s = y;
            #pragma unroll
            for (int o = 1; o < 32; o <<= 1) {
                int t = __shfl_up_sync(0xFFFFFFFFu, s, o);
                if (lane >= o) s += t;
            }
            wsum[lane] = s - y;   // exclusive warp offsets
        }
        __syncthreads();
        int excl = carry_s + wsum[wid] + x - v;
        if (i < n) {
            g_rowptr[i] = excl;
            g_invdeg[i] = 1.0f / fmaxf((float)v, 1.0f);
        }
        __syncthreads();   // everyone has consumed carry_s
        if (tid == 1023) carry_s = carry_s + wsum[31] + x;  // block total
        __syncthreads();
    }
    if (tid == 0) g_rowptr[n] = carry_s;
}

__global__ void k_fill(const int* __restrict__ ei, int E, int n) {
    int e = blockIdx.x * blockDim.x + threadIdx.x;
    if (e < E) {
        int d = ei[E + e];
        int s = ei[e];
        d = min(max(d, 0), n - 1);
        s = min(max(s, 0), n - 1);
        int pos = atomicAdd(&g_cursor[d], 1);
        int slot = g_rowptr[d] + pos;
        if (slot < MAX_E) g_csr_src[slot] = s;
    }
}

// ---------------- mean aggregation: one warp per dst node ----------------
__global__ __launch_bounds__(256) void k_aggregate(const float* __restrict__ feat_ext,
                                                   int n, int use_h) {
    const float* __restrict__ feat = use_h ? (const float*)g_h : feat_ext;
    int gw   = (blockIdx.x * blockDim.x + threadIdx.x) >> 5;  // node
    int lane = threadIdx.x & 31;
    if (gw >= n) return;
    int beg = g_rowptr[gw];
    int end = g_rowptr[gw + 1];
    float4 acc = make_float4(0.f, 0.f, 0.f, 0.f);
    for (int e = beg; e < end; e++) {
        int s = g_csr_src[e];
        float4 v = *(const float4*)&feat[(size_t)s * D + lane * 4];
        acc.x += v.x; acc.y += v.y; acc.z += v.z; acc.w += v.w;
    }
    float inv = g_invdeg[gw];
    acc.x *= inv; acc.y *= inv; acc.z *= inv; acc.w *= inv;
    *(float4*)&g_agg[(size_t)gw * D + lane * 4] = acc;
}

// ---------------- fused GEMM: out = agg@Wl + in@Wr + b (opt relu) ----------
// CTA tile: 64 nodes x 128 cols, K streamed in chunks of 32 (8 chunks: 4 Wl, 4 Wr)
#define TM 64
#define KB 32
__global__ __launch_bounds__(256) void k_gemm(const float* __restrict__ in_ext,
                                              const float* __restrict__ Wl,
                                              const float* __restrict__ Wr,
                                              const float* __restrict__ bias,
                                              float* __restrict__ out_ext,
                                              int n, int use_h_in, int out_to_h,
                                              int do_relu) {
    __shared__ float sA[TM][KB];     // [node][k]
    __shared__ float sB[KB][D];      // [k][col]

    const float* __restrict__ A2 = use_h_in ? (const float*)g_h : in_ext;
    float* __restrict__ out = out_to_h ? (float*)g_h : out_ext;

    int tid = threadIdx.x;
    int tx  = tid & 31;   // col group: cols tx*4 .. tx*4+3
    int ty  = tid >> 5;   // node group: nodes ty*8 .. ty*8+7
    int n0  = blockIdx.x * TM;

    float acc[8][4];
    #pragma unroll
    for (int i = 0; i < 8; i++)
        #pragma unroll
        for (int j = 0; j < 4; j++) acc[i][j] = 0.f;

    #pragma unroll 1
    for (int chunk = 0; chunk < 8; chunk++) {
        const float* __restrict__ A = (chunk < 4) ? (const float*)g_agg : A2;
        const float* __restrict__ W = (chunk < 4) ? Wl : Wr;
        int k0 = (chunk & 3) * KB;

        // load A tile: 64 nodes x 32 k  (512 float4, 2 per thread)
        #pragma unroll
        for (int r = 0; r < 2; r++) {
            int idx  = tid + r * 256;       // 0..511
            int node = idx >> 3;            // 0..63
            int k4   = (idx & 7) * 4;       // 0,4,..,28
            int gn   = n0 + node;
            float4 v = (gn < n) ? *(const float4*)&A[(size_t)gn * D + k0 + k4]
                                : make_float4(0.f, 0.f, 0.f, 0.f);
            *(float4*)&sA[node][k4] = v;
        }
        // load B tile: 32 k x 128 cols  (1024 float4, 4 per thread)
        #pragma unroll
        for (int r = 0; r < 4; r++) {
            int idx = tid + r * 256;        // 0..1023
            int k   = idx >> 5;             // 0..31
            int c4  = (idx & 31) * 4;
            *(float4*)&sB[k][c4] = *(const float4*)&W[(size_t)(k0 + k) * D + c4];
        }
        __syncthreads();

        #pragma unroll 8
        for (int k = 0; k < KB; k++) {
            float4 b4 = *(float4*)&sB[k][tx << 2];
            #pragma unroll
            for (int i = 0; i < 8; i++) {
                float a = sA[ty * 8 + i][k];   // broadcast within warp
                acc[i][0] += a * b4.x;
                acc[i][1] += a * b4.y;
                acc[i][2] += a * b4.z;
                acc[i][3] += a * b4.w;
            }
        }
        __syncthreads();
    }

    float4 bv = *(const float4*)&bias[tx << 2];
    #pragma unroll
    for (int i = 0; i < 8; i++) {
        int gn = n0 + ty * 8 + i;
        if (gn < n) {
            float4 r;
            r.x = acc[i][0] + bv.x;
            r.y = acc[i][1] + bv.y;
            r.z = acc[i][2] + bv.z;
            r.w = acc[i][3] + bv.w;
            if (do_relu) {
                r.x = fmaxf(r.x, 0.f); r.y = fmaxf(r.y, 0.f);
                r.z = fmaxf(r.z, 0.f); r.w = fmaxf(r.w, 0.f);
            }
            *(float4*)&out[(size_t)gn * D + (tx << 2)] = r;
        }
    }
}

// ---------------- launch ----------------
extern "C" void kernel_launch(void* const* d_in, const int* in_sizes, int n_in,
                              void* d_out, int out_size) {
    const float* x   = (const float*)d_in[0];
    const int*   ei  = (const int*)d_in[1];     // int32 edge_index (JAX x64 off)
    const float* W1l = (const float*)d_in[2];
    const float* b1  = (const float*)d_in[3];
    const float* W1r = (const float*)d_in[4];
    const float* W2l = (const float*)d_in[5];
    const float* b2  = (const float*)d_in[6];
    const float* W2r = (const float*)d_in[7];
    float* out = (float*)d_out;

    int n = in_sizes[0] / D;
    int E = in_sizes[1] / 2;

    // CSR build
    k_zero <<<(n + 255) / 256, 256>>>(n);
    k_count<<<(E + 255) / 256, 256>>>(ei, E, n);
    k_scan <<<1, 1024>>>(n);
    k_fill <<<(E + 255) / 256, 256>>>(ei, E, n);

    int agg_blocks  = (n * 32 + 255) / 256;   // one warp per node
    int gemm_blocks = (n + TM - 1) / TM;

    // layer 1: agg(x) ; h = relu(agg@W1l + x@W1r + b1)
    k_aggregate<<<agg_blocks, 256>>>(x, n, /*use_h=*/0);
    k_gemm<<<gemm_blocks, 256>>>(x, W1l, W1r, b1, out, n,
                                 /*use_h_in=*/0, /*out_to_h=*/1, /*relu=*/1);

    // layer 2: agg(h) ; out = agg@W2l + h@W2r + b2
    k_aggregate<<<agg_blocks, 256>>>(x, n, /*use_h=*/1);
    k_gemm<<<gemm_blocks, 256>>>(x, W2l, W2r, b2, out, n,
                                 /*use_h_in=*/1, /*out_to_h=*/0, /*relu=*/0);
}

// round 4
// speedup vs baseline: 1.5070x; 1.5070x over previous
#include <cuda_runtime.h>
#include <cuda_bf16.h>
#include <cstdint>

// ---------------- problem constants ----------------
#define MAX_N 50000
#define MAX_E 800000
#define D 128

// ---------------- device-global scratch ----------------
__device__ int   g_counts[MAX_N];
__device__ int   g_cursor[MAX_N];
__device__ int   g_rowptr[MAX_N + 1];
__device__ int   g_csr_src[MAX_E];
__device__ float g_invdeg[MAX_N];
__device__ float g_agg[(size_t)MAX_N * D];
__device__ float g_h[(size_t)MAX_N * D];
// bf16 hi/lo weight images, transposed: [layer][chunk(8)][n=128][k=32]
__device__ __nv_bfloat16 g_Bh[2][8][128 * 32];
__device__ __nv_bfloat16 g_Bl[2][8][128 * 32];

// ---------------- CSR build ----------------
__global__ void k_zero(int n) {
    int i = blockIdx.x * blockDim.x + threadIdx.x;
    if (i < n) { g_counts[i] = 0; g_cursor[i] = 0; }
}
__global__ void k_count(const int* __restrict__ ei, int E, int n) {
    int e = blockIdx.x * blockDim.x + threadIdx.x;
    if (e < E) {
        int d = ei[E + e];
        d = min(max(d, 0), n - 1);
        atomicAdd(&g_counts[d], 1);
    }
}
__global__ __launch_bounds__(1024) void k_scan(int n) {
    __shared__ int wsum[32];
    __shared__ int carry_s;
    int tid = threadIdx.x, lane = tid & 31, wid = tid >> 5;
    if (tid == 0) carry_s = 0;
    __syncthreads();
    for (int base = 0; base < n; base += 1024) {
        int i = base + tid;
        int v = (i < n) ? g_counts[i] : 0;
        int x = v;
        #pragma unroll
        for (int o = 1; o < 32; o <<= 1) { int t = __shfl_up_sync(~0u, x, o); if (lane >= o) x += t; }
        if (lane == 31) wsum[wid] = x;
        __syncthreads();
        if (wid == 0) {
            int y = wsum[lane], s = y;
            #pragma unroll
            for (int o = 1; o < 32; o <<= 1) { int t = __shfl_up_sync(~0u, s, o); if (lane >= o) s += t; }
            wsum[lane] = s - y;
        }
        __syncthreads();
        int excl = carry_s + wsum[wid] + x - v;
        if (i < n) { g_rowptr[i] = excl; g_invdeg[i] = 1.0f / fmaxf((float)v, 1.0f); }
        __syncthreads();
        if (tid == 1023) carry_s = carry_s + wsum[31] + x;
        __syncthreads();
    }
    if (tid == 0) g_rowptr[n] = carry_s;
}
__global__ void k_fill(const int* __restrict__ ei, int E, int n) {
    int e = blockIdx.x * blockDim.x + threadIdx.x;
    if (e < E) {
        int d = ei[E + e];
        int s = ei[e];
        d = min(max(d, 0), n - 1);
        s = min(max(s, 0), n - 1);
        int pos = atomicAdd(&g_cursor[d], 1);
        int slot = g_rowptr[d] + pos;
        if (slot < MAX_E) g_csr_src[slot] = s;
    }
}

// ---------------- mean aggregation: one warp per dst node ----------------
__global__ __launch_bounds__(256) void k_aggregate(const float* __restrict__ feat_ext,
                                                   int n, int use_h) {
    const float* __restrict__ feat = use_h ? (const float*)g_h : feat_ext;
    int gw = (blockIdx.x * blockDim.x + threadIdx.x) >> 5;
    int lane = threadIdx.x & 31;
    if (gw >= n) return;
    int beg = g_rowptr[gw], end = g_rowptr[gw + 1];
    float4 acc = make_float4(0.f, 0.f, 0.f, 0.f);
    for (int e = beg; e < end; e++) {
        int s = g_csr_src[e];
        float4 v = *(const float4*)&feat[(size_t)s * D + lane * 4];
        acc.x += v.x; acc.y += v.y; acc.z += v.z; acc.w += v.w;
    }
    float inv = g_invdeg[gw];
    acc.x *= inv; acc.y *= inv; acc.z *= inv; acc.w *= inv;
    *(float4*)&g_agg[(size_t)gw * D + lane * 4] = acc;
}

// ---------------- weight prep: transpose + bf16 hi/lo split ----------------
// logical B[n][k], k in [0,256): k<128 -> Wl, else Wr. chunk=k/32, kk=k%32.
__global__ void k_prep_w(const float* __restrict__ Wl1, const float* __restrict__ Wr1,
                         const float* __restrict__ Wl2, const float* __restrict__ Wr2) {
    int idx = blockIdx.x * blockDim.x + threadIdx.x;    // 0..65535
    int l = idx >> 15;
    int r = idx & 32767;
    int k = r >> 7, nn = r & 127;
    const float* Wl = l ? Wl2 : Wl1;
    const float* Wr = l ? Wr2 : Wr1;
    float v = (k < 128) ? Wl[k * 128 + nn] : Wr[(k - 128) * 128 + nn];
    __nv_bfloat16 h = __float2bfloat16(v);
    __nv_bfloat16 lo = __float2bfloat16(v - __bfloat162float(h));
    int chunk = k >> 5, kk = k & 31;
    g_Bh[l][chunk][nn * 32 + kk] = h;
    g_Bl[l][chunk][nn * 32 + kk] = lo;
}

// ---------------- mma.sync helpers ----------------
__device__ __forceinline__ uint32_t smem_u32(const void* p) {
    uint32_t a;
    asm("{ .reg .u64 t; cvta.to.shared.u64 t, %1; cvt.u32.u64 %0, t; }" : "=r"(a) : "l"(p));
    return a;
}
__device__ __forceinline__ void ldm_x4(uint32_t* r, uint32_t addr) {
    asm volatile("ldmatrix.sync.aligned.m8n8.x4.shared.b16 {%0,%1,%2,%3}, [%4];"
                 : "=r"(r[0]), "=r"(r[1]), "=r"(r[2]), "=r"(r[3]) : "r"(addr));
}
__device__ __forceinline__ void mma16816(float* d, const uint32_t* a, uint32_t b0, uint32_t b1) {
    asm volatile("mma.sync.aligned.m16n8k16.row.col.f32.bf16.bf16.f32 "
                 "{%0,%1,%2,%3}, {%4,%5,%6,%7}, {%8,%9}, {%0,%1,%2,%3};"
                 : "+f"(d[0]), "+f"(d[1]), "+f"(d[2]), "+f"(d[3])
                 : "r"(a[0]), "r"(a[1]), "r"(a[2]), "r"(a[3]), "r"(b0), "r"(b1));
}

// ---------------- fused GEMM via mma.sync (bf16 hi/lo x3) ----------------
// out[128 x 128] = [agg | in] @ B + bias (opt relu)
// smem tiles padded: 128 rows x 40 bf16 (80 B stride) -> ldmatrix conflict-free
#define PAD_B 80
__global__ __launch_bounds__(256) void k_gemm_mma(
        const float* __restrict__ in_ext, const float* __restrict__ bias,
        float* __restrict__ out_ext, int n, int layer,
        int use_h_in, int out_to_h, int do_relu) {
    __shared__ __align__(16) char sAh[128 * PAD_B];
    __shared__ __align__(16) char sAl[128 * PAD_B];
    __shared__ __align__(16) char sBh[128 * PAD_B];
    __shared__ __align__(16) char sBl[128 * PAD_B];
    __shared__ float sbias[128];

    const float* __restrict__ A2 = use_h_in ? (const float*)g_h : in_ext;
    float* __restrict__ out = out_to_h ? (float*)g_h : out_ext;

    int tid = threadIdx.x, wid = tid >> 5, lid = tid & 31;
    int n0 = blockIdx.x * 128;
    if (tid < 128) sbias[tid] = bias[tid];

    uint32_t uAh = smem_u32(sAh), uAl = smem_u32(sAl);
    uint32_t uBh = smem_u32(sBh), uBl = smem_u32(sBl);

    // per-lane ldmatrix base offsets
    int rowA  = wid * 16 + (lid & 15);
    int kbA   = (lid >> 4) * 16;
    uint32_t offA = rowA * PAD_B + kbA;
    int rowBl_ = (lid & 7) + ((lid >> 4) << 3);   // within a 16-row ntile pair
    int kbB   = ((lid >> 3) & 1) * 16;
    uint32_t offB = rowBl_ * PAD_B + kbB;

    float acc[16][4];
    #pragma unroll
    for (int t = 0; t < 16; t++)
        #pragma unroll
        for (int j = 0; j < 4; j++) acc[t][j] = 0.f;

    #pragma unroll 1
    for (int c = 0; c < 8; c++) {
        const float* __restrict__ A = (c < 4) ? (const float*)g_agg : A2;
        int k0 = (c & 3) * 32;

        // ---- load A tile: 128 rows x 32 k, fp32 -> bf16 hi/lo ----
        #pragma unroll
        for (int g = 0; g < 2; g++) {
            int idx = tid + g * 256;          // 0..511
            int row = idx >> 2;
            int k8  = (idx & 3) << 3;         // 0,8,16,24
            int gn  = n0 + row;
            float4 v0, v1;
            if (gn < n) {
                const float* p = &A[(size_t)gn * D + k0 + k8];
                v0 = *(const float4*)p;
                v1 = *(const float4*)(p + 4);
            } else {
                v0 = make_float4(0.f, 0.f, 0.f, 0.f);
                v1 = v0;
            }
            float a[8] = {v0.x, v0.y, v0.z, v0.w, v1.x, v1.y, v1.z, v1.w};
            uint32_t hb[4], lb[4];
            #pragma unroll
            for (int j = 0; j < 4; j++) {
                __nv_bfloat16 h0 = __float2bfloat16(a[2 * j]);
                __nv_bfloat16 h1 = __float2bfloat16(a[2 * j + 1]);
                __nv_bfloat16 l0 = __float2bfloat16(a[2 * j] - __bfloat162float(h0));
                __nv_bfloat16 l1 = __float2bfloat16(a[2 * j + 1] - __bfloat162float(h1));
                __nv_bfloat162 hp; hp.x = h0; hp.y = h1;
                __nv_bfloat162 lp; lp.x = l0; lp.y = l1;
                hb[j] = *reinterpret_cast<uint32_t*>(&hp);
                lb[j] = *reinterpret_cast<uint32_t*>(&lp);
            }
            uint32_t doff = row * PAD_B + (k8 << 1);
            *(uint4*)(sAh + doff) = make_uint4(hb[0], hb[1], hb[2], hb[3]);
            *(uint4*)(sAl + doff) = make_uint4(lb[0], lb[1], lb[2], lb[3]);
        }
        // ---- load B tiles: straight copies with padding ----
        {
            const uint4* bh = (const uint4*)g_Bh[layer][c];
            const uint4* bl = (const uint4*)g_Bl[layer][c];
            #pragma unroll
            for (int g = 0; g < 2; g++) {
                int idx = tid + g * 256;      // 0..511
                int row = idx >> 2;
                int c16 = idx & 3;
                uint32_t doff = row * PAD_B + c16 * 16;
                *(uint4*)(sBh + doff) = bh[idx];
                *(uint4*)(sBl + doff) = bl[idx];
            }
        }
        __syncthreads();

        // ---- compute: 2 ksteps x 8 ntile-pairs x 3 products ----
        #pragma unroll
        for (int ks = 0; ks < 2; ks++) {
            uint32_t ah[4], al[4];
            ldm_x4(ah, uAh + offA + ks * 32);
            ldm_x4(al, uAl + offA + ks * 32);
            #pragma unroll
            for (int t2 = 0; t2 < 8; t2++) {
                uint32_t bh[4], bl[4];
                uint32_t boff = offB + t2 * (16 * PAD_B) + ks * 32;
                ldm_x4(bh, uBh + boff);
                ldm_x4(bl, uBl + boff);
                mma16816(acc[2 * t2],     ah, bh[0], bh[1]);
                mma16816(acc[2 * t2],     ah, bl[0], bl[1]);
                mma16816(acc[2 * t2],     al, bh[0], bh[1]);
                mma16816(acc[2 * t2 + 1], ah, bh[2], bh[3]);
                mma16816(acc[2 * t2 + 1], ah, bl[2], bl[3]);
                mma16816(acc[2 * t2 + 1], al, bh[2], bh[3]);
            }
        }
        __syncthreads();
    }

    // ---- epilogue: bias + relu, direct stores ----
    int r0 = n0 + wid * 16 + (lid >> 2);
    int r1 = r0 + 8;
    int cb = (lid & 3) * 2;
    #pragma unroll
    for (int t = 0; t < 16; t++) {
        int col = t * 8 + cb;
        float b0 = sbias[col], b1 = sbias[col + 1];
        float v0 = acc[t][0] + b0, v1 = acc[t][1] + b1;
        float v2 = acc[t][2] + b0, v3 = acc[t][3] + b1;
        if (do_relu) {
            v0 = fmaxf(v0, 0.f); v1 = fmaxf(v1, 0.f);
            v2 = fmaxf(v2, 0.f); v3 = fmaxf(v3, 0.f);
        }
        if (r0 < n) *(float2*)&out[(size_t)r0 * D + col] = make_float2(v0, v1);
        if (r1 < n) *(float2*)&out[(size_t)r1 * D + col] = make_float2(v2, v3);
    }
}

// ---------------- launch ----------------
extern "C" void kernel_launch(void* const* d_in, const int* in_sizes, int n_in,
                              void* d_out, int out_size) {
    const float* x   = (const float*)d_in[0];
    const int*   ei  = (const int*)d_in[1];     // int32 edge_index
    const float* W1l = (const float*)d_in[2];
    const float* b1  = (const float*)d_in[3];
    const float* W1r = (const float*)d_in[4];
    const float* W2l = (const float*)d_in[5];
    const float* b2  = (const float*)d_in[6];
    const float* W2r = (const float*)d_in[7];
    float* out = (float*)d_out;

    int n = in_sizes[0] / D;
    int E = in_sizes[1] / 2;

    // CSR build
    k_zero <<<(n + 255) / 256, 256>>>(n);
    k_count<<<(E + 255) / 256, 256>>>(ei, E, n);
    k_scan <<<1, 1024>>>(n);
    k_fill <<<(E + 255) / 256, 256>>>(ei, E, n);

    // weight prep (both layers)
    k_prep_w<<<256, 256>>>(W1l, W1r, W2l, W2r);

    int agg_blocks  = (n * 32 + 255) / 256;
    int gemm_blocks = (n + 127) / 128;

    // layer 1: h = relu(agg(x)@W1l + x@W1r + b1)
    k_aggregate<<<agg_blocks, 256>>>(x, n, 0);
    k_gemm_mma<<<gemm_blocks, 256>>>(x, b1, out, n, 0, /*use_h_in=*/0, /*out_to_h=*/1, /*relu=*/1);

    // layer 2: out = agg(h)@W2l + h@W2r + b2
    k_aggregate<<<agg_blocks, 256>>>(x, n, 1);
    k_gemm_mma<<<gemm_blocks, 256>>>(x, b2, out, n, 1, /*use_h_in=*/1, /*out_to_h=*/0, /*relu=*/0);
}

// round 5
// speedup vs baseline: 1.8858x; 1.2513x over previous
#include <cuda_runtime.h>
#include <cuda_bf16.h>
#include <cstdint>

// ---------------- problem constants ----------------
#define MAX_N 50000
#define MAX_E 800000
#define D 128
#define CAP 96          // bucket slots per node (deg ~ Poisson(16))

// ---------------- device-global scratch ----------------
__device__ int g_cursor[MAX_N];
__device__ int g_bucket[(size_t)MAX_N * CAP];
// bf16 hi/lo feature planes, each [node][64] u32 (= 128 bf16 per row, 256B)
__device__ __align__(128) uint32_t g_xh[(size_t)MAX_N * 64];
__device__ __align__(128) uint32_t g_xl[(size_t)MAX_N * 64];
__device__ __align__(128) uint32_t g_ah[(size_t)MAX_N * 64];
__device__ __align__(128) uint32_t g_al[(size_t)MAX_N * 64];
__device__ __align__(128) uint32_t g_hh[(size_t)MAX_N * 64];
__device__ __align__(128) uint32_t g_hl[(size_t)MAX_N * 64];
// bf16 hi/lo weight images, transposed: [layer][chunk(8)][n=128][k=32]
__device__ __align__(128) __nv_bfloat16 g_Bh[2][8][128 * 32];
__device__ __align__(128) __nv_bfloat16 g_Bl[2][8][128 * 32];

// ---------------- small helpers ----------------
__device__ __forceinline__ uint32_t pack_bf2(float a, float b) {
    __nv_bfloat162 t;
    t.x = __float2bfloat16(a);
    t.y = __float2bfloat16(b);
    return *reinterpret_cast<uint32_t*>(&t);
}
__device__ __forceinline__ float bf_res(float v) {
    return v - __bfloat162float(__float2bfloat16(v));
}
__device__ __forceinline__ float bf_lo(uint32_t u) { return __uint_as_float(u << 16); }
__device__ __forceinline__ float bf_hi(uint32_t u) { return __uint_as_float(u & 0xFFFF0000u); }

__device__ __forceinline__ uint32_t smem_u32(const void* p) {
    uint32_t a;
    asm("{ .reg .u64 t; cvta.to.shared.u64 t, %1; cvt.u32.u64 %0, t; }" : "=r"(a) : "l"(p));
    return a;
}
__device__ __forceinline__ void ldm_x4(uint32_t* r, uint32_t addr) {
    asm volatile("ldmatrix.sync.aligned.m8n8.x4.shared.b16 {%0,%1,%2,%3}, [%4];"
                 : "=r"(r[0]), "=r"(r[1]), "=r"(r[2]), "=r"(r[3]) : "r"(addr));
}
__device__ __forceinline__ void mma16816(float* d, const uint32_t* a, uint32_t b0, uint32_t b1) {
    asm volatile("mma.sync.aligned.m16n8k16.row.col.f32.bf16.bf16.f32 "
                 "{%0,%1,%2,%3}, {%4,%5,%6,%7}, {%8,%9}, {%0,%1,%2,%3};"
                 : "+f"(d[0]), "+f"(d[1]), "+f"(d[2]), "+f"(d[3])
                 : "r"(a[0]), "r"(a[1]), "r"(a[2]), "r"(a[3]), "r"(b0), "r"(b1));
}
__device__ __forceinline__ void cp16(uint32_t dst, const void* src, uint32_t sz) {
    asm volatile("cp.async.cg.shared.global [%0], [%1], 16, %2;"
                 :: "r"(dst), "l"(src), "r"(sz) : "memory");
}
#define CP_COMMIT()  asm volatile("cp.async.commit_group;" ::: "memory")
#define CP_WAIT(N)   asm volatile("cp.async.wait_group %0;" :: "n"(N) : "memory")

// XOR swizzle: 64B rows, 4x16B chunks; conflict-free for ldmatrix
#define SWZ(row, ci) (((uint32_t)(row) << 6) + (((((ci) ^ ((row) >> 1)) & 3)) << 4))

// ---------------- graph build: single-pass bucket scatter ----------------
__global__ void k_zero(int n) {
    int i = blockIdx.x * blockDim.x + threadIdx.x;
    if (i < n) g_cursor[i] = 0;
}
__global__ void k_scatter(const int* __restrict__ ei, int E, int n) {
    int e = blockIdx.x * blockDim.x + threadIdx.x;
    if (e < E) {
        int d = ei[E + e];
        int s = ei[e];
        d = min(max(d, 0), n - 1);
        s = min(max(s, 0), n - 1);
        int pos = atomicAdd(&g_cursor[d], 1);
        if (pos < CAP) g_bucket[(size_t)d * CAP + pos] = s;
    }
}

// ---------------- x -> bf16 hi/lo planes ----------------
__global__ void k_split_x(const float* __restrict__ x, int total64) {
    int i = blockIdx.x * blockDim.x + threadIdx.x;
    if (i < total64) {
        float2 v = ((const float2*)x)[i];
        g_xh[i] = pack_bf2(v.x, v.y);
        g_xl[i] = pack_bf2(bf_res(v.x), bf_res(v.y));
    }
}

// ---------------- weight prep: transpose + bf16 hi/lo split ----------------
__global__ void k_prep_w(const float* __restrict__ Wl1, const float* __restrict__ Wr1,
                         const float* __restrict__ Wl2, const float* __restrict__ Wr2) {
    int idx = blockIdx.x * blockDim.x + threadIdx.x;    // 0..65535
    int l = idx >> 15;
    int r = idx & 32767;
    int k = r >> 7, nn = r & 127;
    const float* Wl = l ? Wl2 : Wl1;
    const float* Wr = l ? Wr2 : Wr1;
    float v = (k < 128) ? Wl[k * 128 + nn] : Wr[(k - 128) * 128 + nn];
    int chunk = k >> 5, kk = k & 31;
    g_Bh[l][chunk][nn * 32 + kk] = __float2bfloat16(v);
    g_Bl[l][chunk][nn * 32 + kk] = __float2bfloat16(bf_res(v));
}

// ---------------- mean aggregation: warp per node, plane gather ----------------
__global__ __launch_bounds__(256) void k_agg(int n, int sel) {
    const uint32_t* __restrict__ fh = sel ? g_hh : g_xh;
    const uint32_t* __restrict__ fl = sel ? g_hl : g_xl;
    int gw = (blockIdx.x * blockDim.x + threadIdx.x) >> 5;
    int lane = threadIdx.x & 31;
    if (gw >= n) return;
    int deg = g_cursor[gw];
    deg = min(deg, CAP);
    float inv = 1.0f / (float)max(deg, 1);
    const int* __restrict__ bk = &g_bucket[(size_t)gw * CAP];
    float a0 = 0.f, a1 = 0.f, a2 = 0.f, a3 = 0.f;
    #pragma unroll 2
    for (int e = 0; e < deg; e++) {
        int s = bk[e];
        size_t o = (size_t)s * 64 + lane * 2;
        uint2 uh = *(const uint2*)&fh[o];
        uint2 ul = *(const uint2*)&fl[o];
        a0 += bf_lo(uh.x) + bf_lo(ul.x);
        a1 += bf_hi(uh.x) + bf_hi(ul.x);
        a2 += bf_lo(uh.y) + bf_lo(ul.y);
        a3 += bf_hi(uh.y) + bf_hi(ul.y);
    }
    a0 *= inv; a1 *= inv; a2 *= inv; a3 *= inv;
    size_t w = (size_t)gw * 64 + lane * 2;
    g_ah[w]     = pack_bf2(a0, a1);
    g_ah[w + 1] = pack_bf2(a2, a3);
    g_al[w]     = pack_bf2(bf_res(a0), bf_res(a1));
    g_al[w + 1] = pack_bf2(bf_res(a2), bf_res(a3));
}

// ---------------- pipelined HMMA GEMM ----------------
// out[128 x 128] = [agg | self] @ B + bias; K=256 in 8 chunks of 32.
// dyn smem: 2 stages x (Ah 8K | Al 8K | Bh 8K | Bl 8K) + bias 512 = 66048 B
#define STAGE_BYTES 32768
#define SM_BIAS_OFF 65536
#define SMEM_TOTAL  66048

__global__ __launch_bounds__(256, 2) void k_gemm(
        const float* __restrict__ bias, float* __restrict__ out,
        int n, int layer, int self_sel, int out_fp32, int do_relu) {
    extern __shared__ char smem[];
    uint32_t sb = smem_u32(smem);
    float* sbias = (float*)(smem + SM_BIAS_OFF);

    int tid = threadIdx.x, wid = tid >> 5, lid = tid & 31;
    int widm = wid & 3, widn = wid >> 2;
    int n0 = blockIdx.x * 128;
    if (tid < 128) sbias[tid] = bias[tid];

    const uint32_t* __restrict__ selfH = self_sel ? g_hh : g_xh;
    const uint32_t* __restrict__ selfL = self_sel ? g_hl : g_xl;

    // per-lane ldmatrix row/ci selectors
    int lA_row = lid & 15, lA_ci = lid >> 4;
    int lB_row = (lid & 7) + ((lid >> 4) << 3), lB_ci = (lid >> 3) & 1;

    float acc[2][8][4];
    #pragma unroll
    for (int mt = 0; mt < 2; mt++)
        #pragma unroll
        for (int nt = 0; nt < 8; nt++)
            #pragma unroll
            for (int j = 0; j < 4; j++) acc[mt][nt][j] = 0.f;

    // ---- async stage loader ----
    auto issue = [&](int c, int st) {
        const uint32_t* pAh = (c < 4) ? g_ah : selfH;
        const uint32_t* pAl = (c < 4) ? g_al : selfL;
        const char* pBh = (const char*)&g_Bh[layer][c][0];
        const char* pBl = (const char*)&g_Bl[layer][c][0];
        uint32_t sa = sb + st * STAGE_BYTES;
        int koff = (c & 3) * 16;   // u32 offset within 256B row
        #pragma unroll
        for (int g = 0; g < 2; g++) {
            int idx = tid + g * 256;          // 0..511
            int row = idx >> 2, ci = idx & 3;
            int gn = n0 + row;
            uint32_t ok = (gn < n) ? 16u : 0u;
            int gnc = (gn < n) ? gn : 0;
            const char* sh = (const char*)(pAh + (size_t)gnc * 64 + koff + ci * 4);
            const char* sl = (const char*)(pAl + (size_t)gnc * 64 + koff + ci * 4);
            uint32_t d0 = sa + SWZ(row, ci);
            cp16(d0,         sh, ok);
            cp16(d0 + 8192,  sl, ok);
            cp16(d0 + 16384, pBh + row * 64 + ci * 16, 16u);
            cp16(d0 + 24576, pBl + row * 64 + ci * 16, 16u);
        }
    };

    issue(0, 0);
    CP_COMMIT();

    #pragma unroll 1
    for (int c = 0; c < 8; c++) {
        if (c < 7) { issue(c + 1, (c + 1) & 1); CP_COMMIT(); CP_WAIT(1); }
        else       { CP_WAIT(0); }
        __syncthreads();

        uint32_t base = sb + (c & 1) * STAGE_BYTES;
        #pragma unroll
        for (int ks = 0; ks < 2; ks++) {
            int ciA = ks * 2 + lA_ci;
            uint32_t ah[2][4], al[2][4];
            #pragma unroll
            for (int mt = 0; mt < 2; mt++) {
                int row = widm * 32 + mt * 16 + lA_row;
                uint32_t off = SWZ(row, ciA);
                ldm_x4(ah[mt], base + off);
                ldm_x4(al[mt], base + 8192 + off);
            }
            int ciB = ks * 2 + lB_ci;
            uint32_t boff[4];
            uint32_t bf[4][4];
            #pragma unroll
            for (int g = 0; g < 4; g++) {
                int row = widn * 64 + g * 16 + lB_row;
                boff[g] = SWZ(row, ciB);
                ldm_x4(bf[g], base + 16384 + boff[g]);
            }
            // hi*Bh + lo*Bh
            #pragma unroll
            for (int mt = 0; mt < 2; mt++)
                #pragma unroll
                for (int g = 0; g < 4; g++) {
                    mma16816(acc[mt][2 * g],     ah[mt], bf[g][0], bf[g][1]);
                    mma16816(acc[mt][2 * g + 1], ah[mt], bf[g][2], bf[g][3]);
                    mma16816(acc[mt][2 * g],     al[mt], bf[g][0], bf[g][1]);
                    mma16816(acc[mt][2 * g + 1], al[mt], bf[g][2], bf[g][3]);
                }
            // hi*Bl
            #pragma unroll
            for (int g = 0; g < 4; g++)
                ldm_x4(bf[g], base + 24576 + boff[g]);
            #pragma unroll
            for (int mt = 0; mt < 2; mt++)
                #pragma unroll
                for (int g = 0; g < 4; g++) {
                    mma16816(acc[mt][2 * g],     ah[mt], bf[g][0], bf[g][1]);
                    mma16816(acc[mt][2 * g + 1], ah[mt], bf[g][2], bf[g][3]);
                }
        }
        __syncthreads();
    }

    // ---- epilogue ----
    int lr = lid >> 2, lc = (lid & 3) * 2;
    #pragma unroll
    for (int mt = 0; mt < 2; mt++) {
        #pragma unroll
        for (int pr = 0; pr < 2; pr++) {
            int gn = n0 + widm * 32 + mt * 16 + lr + pr * 8;
            if (gn >= n) continue;
            #pragma unroll
            for (int nt = 0; nt < 8; nt++) {
                int col = widn * 64 + nt * 8 + lc;
                float v0 = acc[mt][nt][pr * 2]     + sbias[col];
                float v1 = acc[mt][nt][pr * 2 + 1] + sbias[col + 1];
                if (do_relu) { v0 = fmaxf(v0, 0.f); v1 = fmaxf(v1, 0.f); }
                if (out_fp32) {
                    *(float2*)&out[(size_t)gn * D + col] = make_float2(v0, v1);
                } else {
                    size_t w = (size_t)gn * 64 + (col >> 1);
                    g_hh[w] = pack_bf2(v0, v1);
                    g_hl[w] = pack_bf2(bf_res(v0), bf_res(v1));
                }
            }
        }
    }
}

// ---------------- launch ----------------
extern "C" void kernel_launch(void* const* d_in, const int* in_sizes, int n_in,
                              void* d_out, int out_size) {
    const float* x   = (const float*)d_in[0];
    const int*   ei  = (const int*)d_in[1];     // int32 edge_index
    const float* W1l = (const float*)d_in[2];
    const float* b1  = (const float*)d_in[3];
    const float* W1r = (const float*)d_in[4];
    const float* W2l = (const float*)d_in[5];
    const float* b2  = (const float*)d_in[6];
    const float* W2r = (const float*)d_in[7];
    float* out = (float*)d_out;

    int n = in_sizes[0] / D;
    int E = in_sizes[1] / 2;

    static int smem_set = 0;
    if (!smem_set) {
        cudaFuncSetAttribute(k_gemm, cudaFuncAttributeMaxDynamicSharedMemorySize, SMEM_TOTAL);
        smem_set = 1;
    }

    // graph build + prep
    k_zero   <<<(n + 255) / 256, 256>>>(n);
    k_scatter<<<(E + 255) / 256, 256>>>(ei, E, n);
    k_prep_w <<<256, 256>>>(W1l, W1r, W2l, W2r);
    k_split_x<<<(n * 64 + 255) / 256, 256>>>(x, n * 64);

    int agg_blocks  = (n * 32 + 255) / 256;
    int gemm_blocks = (n + 127) / 128;

    // layer 1: h = relu(agg(x)@W1l + x@W1r + b1)  -> hi/lo planes
    k_agg <<<agg_blocks, 256>>>(n, 0);
    k_gemm<<<gemm_blocks, 256, SMEM_TOTAL>>>(b1, out, n, 0, /*self=x*/0, /*fp32*/0, /*relu*/1);

    // layer 2: out = agg(h)@W2l + h@W2r + b2  -> fp32 d_out
    k_agg <<<agg_blocks, 256>>>(n, 1);
    k_gemm<<<gemm_blocks, 256, SMEM_TOTAL>>>(b2, out, n, 1, /*self=h*/1, /*fp32*/1, /*relu*/0);
}

// round 6
// speedup vs baseline: 1.8873x; 1.0008x over previous
#include <cuda_runtime.h>
#include <cuda_bf16.h>
#include <cstdint>

// ---------------- problem constants ----------------
#define MAX_N 50000
#define MAX_E 800000
#define D 128
#define CAP 96          // bucket slots per node (deg ~ Poisson(16))

// ---------------- device-global scratch ----------------
__device__ int g_cursor[MAX_N];
__device__ int g_bucket[(size_t)MAX_N * CAP];
// bf16 hi/lo feature planes, each [node][64] u32 (= 128 bf16 per row, 256B)
__device__ __align__(128) uint32_t g_xh[(size_t)MAX_N * 64];
__device__ __align__(128) uint32_t g_xl[(size_t)MAX_N * 64];
__device__ __align__(128) uint32_t g_ah[(size_t)MAX_N * 64];
__device__ __align__(128) uint32_t g_al[(size_t)MAX_N * 64];
__device__ __align__(128) uint32_t g_hh[(size_t)MAX_N * 64];
__device__ __align__(128) uint32_t g_hl[(size_t)MAX_N * 64];
// bf16 hi/lo weight images, transposed: [layer][chunk(8)][n=128][k=32]
__device__ __align__(128) __nv_bfloat16 g_Bh[2][8][128 * 32];
__device__ __align__(128) __nv_bfloat16 g_Bl[2][8][128 * 32];

// ---------------- small helpers ----------------
__device__ __forceinline__ uint32_t pack_bf2(float a, float b) {
    __nv_bfloat162 t;
    t.x = __float2bfloat16(a);
    t.y = __float2bfloat16(b);
    return *reinterpret_cast<uint32_t*>(&t);
}
__device__ __forceinline__ float bf_res(float v) {
    return v - __bfloat162float(__float2bfloat16(v));
}
__device__ __forceinline__ float bf_lo(uint32_t u) { return __uint_as_float(u << 16); }
__device__ __forceinline__ float bf_hi(uint32_t u) { return __uint_as_float(u & 0xFFFF0000u); }

__device__ __forceinline__ uint32_t smem_u32(const void* p) {
    uint32_t a;
    asm("{ .reg .u64 t; cvta.to.shared.u64 t, %1; cvt.u32.u64 %0, t; }" : "=r"(a) : "l"(p));
    return a;
}
__device__ __forceinline__ void ldm_x4(uint32_t* r, uint32_t addr) {
    asm volatile("ldmatrix.sync.aligned.m8n8.x4.shared.b16 {%0,%1,%2,%3}, [%4];"
                 : "=r"(r[0]), "=r"(r[1]), "=r"(r[2]), "=r"(r[3]) : "r"(addr));
}
__device__ __forceinline__ void mma16816(float* d, const uint32_t* a, uint32_t b0, uint32_t b1) {
    asm volatile("mma.sync.aligned.m16n8k16.row.col.f32.bf16.bf16.f32 "
                 "{%0,%1,%2,%3}, {%4,%5,%6,%7}, {%8,%9}, {%0,%1,%2,%3};"
                 : "+f"(d[0]), "+f"(d[1]), "+f"(d[2]), "+f"(d[3])
                 : "r"(a[0]), "r"(a[1]), "r"(a[2]), "r"(a[3]), "r"(b0), "r"(b1));
}
__device__ __forceinline__ void cp16(uint32_t dst, const void* src, uint32_t sz) {
    asm volatile("cp.async.cg.shared.global [%0], [%1], 16, %2;"
                 :: "r"(dst), "l"(src), "r"(sz) : "memory");
}
#define CP_COMMIT()  asm volatile("cp.async.commit_group;" ::: "memory")
#define CP_WAIT(N)   asm volatile("cp.async.wait_group %0;" :: "n"(N) : "memory")

// XOR swizzle: 64B rows, 4x16B chunks; conflict-free for ldmatrix
#define SWZ(row, ci) (((uint32_t)(row) << 6) + (((((ci) ^ ((row) >> 1)) & 3)) << 4))

// ---------------- graph build: single-pass bucket scatter ----------------
__global__ void k_zero(int n) {
    int i = blockIdx.x * blockDim.x + threadIdx.x;
    if (i < n) g_cursor[i] = 0;
}
__global__ void k_scatter(const int* __restrict__ ei, int E2, int n) {
    int t = blockIdx.x * blockDim.x + threadIdx.x;   // handles 2 edges
    if (t < E2) {
        int2 sp = ((const int2*)ei)[t];
        int2 dp = ((const int2*)(ei + 2 * E2))[t];
        int d0 = min(max(dp.x, 0), n - 1), s0 = min(max(sp.x, 0), n - 1);
        int d1 = min(max(dp.y, 0), n - 1), s1 = min(max(sp.y, 0), n - 1);
        int p0 = atomicAdd(&g_cursor[d0], 1);
        if (p0 < CAP) g_bucket[(size_t)d0 * CAP + p0] = s0;
        int p1 = atomicAdd(&g_cursor[d1], 1);
        if (p1 < CAP) g_bucket[(size_t)d1 * CAP + p1] = s1;
    }
}

// ---------------- x -> bf16 hi/lo planes ----------------
__global__ void k_split_x(const float* __restrict__ x, int total64) {
    int i = blockIdx.x * blockDim.x + threadIdx.x;
    if (i < total64) {
        float2 v = ((const float2*)x)[i];
        g_xh[i] = pack_bf2(v.x, v.y);
        g_xl[i] = pack_bf2(bf_res(v.x), bf_res(v.y));
    }
}

// ---------------- weight prep: transpose + bf16 hi/lo split ----------------
__global__ void k_prep_w(const float* __restrict__ Wl1, const float* __restrict__ Wr1,
                         const float* __restrict__ Wl2, const float* __restrict__ Wr2) {
    int idx = blockIdx.x * blockDim.x + threadIdx.x;    // 0..65535
    int l = idx >> 15;
    int r = idx & 32767;
    int k = r >> 7, nn = r & 127;
    const float* Wl = l ? Wl2 : Wl1;
    const float* Wr = l ? Wr2 : Wr1;
    float v = (k < 128) ? Wl[k * 128 + nn] : Wr[(k - 128) * 128 + nn];
    int chunk = k >> 5, kk = k & 31;
    g_Bh[l][chunk][nn * 32 + kk] = __float2bfloat16(v);
    g_Bl[l][chunk][nn * 32 + kk] = __float2bfloat16(bf_res(v));
}

// ---------------- mean aggregation: warp per node, plane gather ----------------
__global__ __launch_bounds__(256) void k_agg(int n, int sel) {
    const uint32_t* __restrict__ fh = sel ? g_hh : g_xh;
    const uint32_t* __restrict__ fl = sel ? g_hl : g_xl;
    int gw = (blockIdx.x * blockDim.x + threadIdx.x) >> 5;
    int lane = threadIdx.x & 31;
    if (gw >= n) return;
    int deg = g_cursor[gw];
    deg = min(deg, CAP);
    float inv = 1.0f / (float)max(deg, 1);
    const int* __restrict__ bk = &g_bucket[(size_t)gw * CAP];
    float a0 = 0.f, a1 = 0.f, a2 = 0.f, a3 = 0.f;
    #pragma unroll 2
    for (int e = 0; e < deg; e++) {
        int s = bk[e];
        size_t o = (size_t)s * 64 + lane * 2;
        uint2 uh = *(const uint2*)&fh[o];
        uint2 ul = *(const uint2*)&fl[o];
        a0 += bf_lo(uh.x) + bf_lo(ul.x);
        a1 += bf_hi(uh.x) + bf_hi(ul.x);
        a2 += bf_lo(uh.y) + bf_lo(ul.y);
        a3 += bf_hi(uh.y) + bf_hi(ul.y);
    }
    a0 *= inv; a1 *= inv; a2 *= inv; a3 *= inv;
    size_t w = (size_t)gw * 64 + lane * 2;
    g_ah[w]     = pack_bf2(a0, a1);
    g_ah[w + 1] = pack_bf2(a2, a3);
    g_al[w]     = pack_bf2(bf_res(a0), bf_res(a1));
    g_al[w + 1] = pack_bf2(bf_res(a2), bf_res(a3));
}

// ---------------- pipelined HMMA GEMM (3-stage) ----------------
// out[128 x 128] = [agg | self] @ B + bias; K=256 in 8 chunks of 32.
// dyn smem: 3 stages x (Ah 8K | Al 8K | Bh 8K | Bl 8K) + bias 512 = 98816 B
#define STAGE_BYTES 32768
#define NSTAGE 3
#define SM_BIAS_OFF (NSTAGE * STAGE_BYTES)
#define SMEM_TOTAL  (SM_BIAS_OFF + 512)

__global__ __launch_bounds__(256, 2) void k_gemm(
        const float* __restrict__ bias, float* __restrict__ out,
        int n, int layer, int self_sel, int out_fp32, int do_relu) {
    extern __shared__ char smem[];
    uint32_t sb = smem_u32(smem);
    float* sbias = (float*)(smem + SM_BIAS_OFF);

    int tid = threadIdx.x, wid = tid >> 5, lid = tid & 31;
    int widm = wid & 3, widn = wid >> 2;
    int n0 = blockIdx.x * 128;
    if (tid < 128) sbias[tid] = bias[tid];

    const uint32_t* __restrict__ selfH = self_sel ? g_hh : g_xh;
    const uint32_t* __restrict__ selfL = self_sel ? g_hl : g_xl;

    // per-lane ldmatrix row/ci selectors
    int lA_row = lid & 15, lA_ci = lid >> 4;
    int lB_row = (lid & 7) + ((lid >> 4) << 3), lB_ci = (lid >> 3) & 1;

    float acc[2][8][4];
    #pragma unroll
    for (int mt = 0; mt < 2; mt++)
        #pragma unroll
        for (int nt = 0; nt < 8; nt++)
            #pragma unroll
            for (int j = 0; j < 4; j++) acc[mt][nt][j] = 0.f;

    // ---- async stage loader ----
    auto issue = [&](int c, int st) {
        const uint32_t* pAh = (c < 4) ? g_ah : selfH;
        const uint32_t* pAl = (c < 4) ? g_al : selfL;
        const char* pBh = (const char*)&g_Bh[layer][c][0];
        const char* pBl = (const char*)&g_Bl[layer][c][0];
        uint32_t sa = sb + st * STAGE_BYTES;
        int koff = (c & 3) * 16;   // u32 offset within 256B row
        #pragma unroll
        for (int g = 0; g < 2; g++) {
            int idx = tid + g * 256;          // 0..511
            int row = idx >> 2, ci = idx & 3;
            int gn = n0 + row;
            uint32_t ok = (gn < n) ? 16u : 0u;
            int gnc = (gn < n) ? gn : 0;
            const char* sh = (const char*)(pAh + (size_t)gnc * 64 + koff + ci * 4);
            const char* sl = (const char*)(pAl + (size_t)gnc * 64 + koff + ci * 4);
            uint32_t d0 = sa + SWZ(row, ci);
            cp16(d0,         sh, ok);
            cp16(d0 + 8192,  sl, ok);
            cp16(d0 + 16384, pBh + row * 64 + ci * 16, 16u);
            cp16(d0 + 24576, pBl + row * 64 + ci * 16, 16u);
        }
    };

    issue(0, 0); CP_COMMIT();
    issue(1, 1); CP_COMMIT();

    #pragma unroll 1
    for (int c = 0; c < 8; c++) {
        if (c + 2 < 8) { issue(c + 2, (c + 2) % NSTAGE); CP_COMMIT(); CP_WAIT(2); }
        else           { CP_WAIT(0); }
        __syncthreads();

        uint32_t base = sb + (c % NSTAGE) * STAGE_BYTES;
        #pragma unroll
        for (int ks = 0; ks < 2; ks++) {
            int ciA = ks * 2 + lA_ci;
            uint32_t ah[2][4], al[2][4];
            #pragma unroll
            for (int mt = 0; mt < 2; mt++) {
                int row = widm * 32 + mt * 16 + lA_row;
                uint32_t off = SWZ(row, ciA);
                ldm_x4(ah[mt], base + off);
                ldm_x4(al[mt], base + 8192 + off);
            }
            int ciB = ks * 2 + lB_ci;
            uint32_t boff[4];
            uint32_t bf[4][4];
            #pragma unroll
            for (int g = 0; g < 4; g++) {
                int row = widn * 64 + g * 16 + lB_row;
                boff[g] = SWZ(row, ciB);
                ldm_x4(bf[g], base + 16384 + boff[g]);
            }
            // hi*Bh + lo*Bh
            #pragma unroll
            for (int mt = 0; mt < 2; mt++)
                #pragma unroll
                for (int g = 0; g < 4; g++) {
                    mma16816(acc[mt][2 * g],     ah[mt], bf[g][0], bf[g][1]);
                    mma16816(acc[mt][2 * g + 1], ah[mt], bf[g][2], bf[g][3]);
                    mma16816(acc[mt][2 * g],     al[mt], bf[g][0], bf[g][1]);
                    mma16816(acc[mt][2 * g + 1], al[mt], bf[g][2], bf[g][3]);
                }
            // hi*Bl
            #pragma unroll
            for (int g = 0; g < 4; g++)
                ldm_x4(bf[g], base + 24576 + boff[g]);
            #pragma unroll
            for (int mt = 0; mt < 2; mt++)
                #pragma unroll
                for (int g = 0; g < 4; g++) {
                    mma16816(acc[mt][2 * g],     ah[mt], bf[g][0], bf[g][1]);
                    mma16816(acc[mt][2 * g + 1], ah[mt], bf[g][2], bf[g][3]);
                }
        }
        __syncthreads();
    }

    // ---- epilogue ----
    int lr = lid >> 2, lc = (lid & 3) * 2;
    #pragma unroll
    for (int mt = 0; mt < 2; mt++) {
        #pragma unroll
        for (int pr = 0; pr < 2; pr++) {
            int gn = n0 + widm * 32 + mt * 16 + lr + pr * 8;
            if (gn >= n) continue;
            #pragma unroll
            for (int nt = 0; nt < 8; nt++) {
                int col = widn * 64 + nt * 8 + lc;
                float v0 = acc[mt][nt][pr * 2]     + sbias[col];
                float v1 = acc[mt][nt][pr * 2 + 1] + sbias[col + 1];
                if (do_relu) { v0 = fmaxf(v0, 0.f); v1 = fmaxf(v1, 0.f); }
                if (out_fp32) {
                    *(float2*)&out[(size_t)gn * D + col] = make_float2(v0, v1);
                } else {
                    size_t w = (size_t)gn * 64 + (col >> 1);
                    g_hh[w] = pack_bf2(v0, v1);
                    g_hl[w] = pack_bf2(bf_res(v0), bf_res(v1));
                }
            }
        }
    }
}

// ---------------- launch ----------------
extern "C" void kernel_launch(void* const* d_in, const int* in_sizes, int n_in,
                              void* d_out, int out_size) {
    const float* x   = (const float*)d_in[0];
    const int*   ei  = (const int*)d_in[1];     // int32 edge_index
    const float* W1l = (const float*)d_in[2];
    const float* b1  = (const float*)d_in[3];
    const float* W1r = (const float*)d_in[4];
    const float* W2l = (const float*)d_in[5];
    const float* b2  = (const float*)d_in[6];
    const float* W2r = (const float*)d_in[7];
    float* out = (float*)d_out;

    int n = in_sizes[0] / D;
    int E = in_sizes[1] / 2;

    static cudaStream_t sB = nullptr;
    static cudaEvent_t evFork, evJoin;
    if (!sB) {
        cudaFuncSetAttribute(k_gemm, cudaFuncAttributeMaxDynamicSharedMemorySize, SMEM_TOTAL);
        cudaStreamCreateWithFlags(&sB, cudaStreamNonBlocking);
        cudaEventCreateWithFlags(&evFork, cudaEventDisableTiming);
        cudaEventCreateWithFlags(&evJoin, cudaEventDisableTiming);
    }

    // fork: stream B does weight prep + x split while legacy stream builds graph
    cudaEventRecord(evFork, 0);
    cudaStreamWaitEvent(sB, evFork, 0);
    k_prep_w <<<256, 256, 0, sB>>>(W1l, W1r, W2l, W2r);
    k_split_x<<<(n * 64 + 255) / 256, 256, 0, sB>>>(x, n * 64);
    cudaEventRecord(evJoin, sB);

    k_zero   <<<(n + 255) / 256, 256>>>(n);
    k_scatter<<<(E / 2 + 255) / 256, 256>>>(ei, E / 2, n);

    cudaStreamWaitEvent(0, evJoin, 0);   // join before layer 1

    int agg_blocks  = (n * 32 + 255) / 256;
    int gemm_blocks = (n + 127) / 128;

    // layer 1: h = relu(agg(x)@W1l + x@W1r + b1)  -> hi/lo planes
    k_agg <<<agg_blocks, 256>>>(n, 0);
    k_gemm<<<gemm_blocks, 256, SMEM_TOTAL>>>(b1, out, n, 0, /*self=x*/0, /*fp32*/0, /*relu*/1);

    // layer 2: out = agg(h)@W2l + h@W2r + b2  -> fp32 d_out
    k_agg <<<agg_blocks, 256>>>(n, 1);
    k_gemm<<<gemm_blocks, 256, SMEM_TOTAL>>>(b2, out, n, 1, /*self=h*/1, /*fp32*/1, /*relu*/0);
}